// round 8
// baseline (speedup 1.0000x reference)
#include <cuda_runtime.h>
#include <math.h>

// ---------------------------------------------------------------------------
// Compile-time DCT-II matrix (matches reference: PI = 3.1415926 truncated).
// Entries are +/- 0.5*cos(k*pi/16) and sqrt(1/8); fold error vs reference
// < 4e-7. Function-local constexpr => every CD.v[const][const] becomes an
// FFMA immediate operand (imm-form FFMA, rt=1/SMSP; no LDS/LDC).
// ---------------------------------------------------------------------------
struct DCTTab { float v[8][8]; };

__host__ __device__ constexpr DCTTab make_dct() {
    const float ck[9] = {0.5f,        0.49039264f, 0.46193977f, 0.41573481f,
                         0.35355339f, 0.27778512f, 0.19134172f, 0.09754516f,
                         0.0f};
    DCTTab t{};
    for (int i = 0; i < 8; i++) {
        for (int j = 0; j < 8; j++) {
            if (i == 0) { t.v[i][j] = 0.35355339f; continue; }  // sqrt(1/8)
            int a = (i * (2 * j + 1)) % 32;
            float s = 1.0f;
            if (a > 16) a = 32 - a;                  // cos(2pi-x) =  cos(x)
            if (a > 8)  { a = 16 - a; s = -1.0f; }   // cos(pi-x)  = -cos(x)
            t.v[i][j] = s * ck[a];
        }
    }
    return t;
}

__device__ __forceinline__ float gelu_exact(float x) {
    return 0.5f * x * (1.0f + erff(x * 0.70710678f));
}

// ---------------------------------------------------------------------------
// Single fused kernel.
//   * threads 0..63 of each CTA recompute the learned quant matrix
//     (noise MLP -> nr[18]; softmax(qmat_weights); reduce over 16 qmats)
//     into smem. Deterministic, identical across CTAs; removes the separate
//     setup launch (~14us of serialized overhead in R6).
//   * one thread per 8x8 block, whole block in registers. xv is consumed
//     row-by-row during the row DCT (8 floats live, not 64); for the final
//     high = x - low we RE-READ x (expected L2 hit: same CTA touched the
//     line ~10us earlier, L2 turnover ~25us). This drops the live set from
//     ~168 regs to ~110, roughly doubling occupancy.
// ---------------------------------------------------------------------------
__global__ void __launch_bounds__(128)
fused_dct_kernel(const float* __restrict__ x,
                 float* __restrict__ lo,
                 float* __restrict__ hi,
                 const float* __restrict__ noise,
                 const float* __restrict__ qmat,
                 const float* __restrict__ qmw,
                 const float* __restrict__ w1, const float* __restrict__ b1,
                 const float* __restrict__ w2, const float* __restrict__ b2,
                 const float* __restrict__ w3, const float* __restrict__ b3) {
    constexpr DCTTab CD = make_dct();

    __shared__ __align__(16) float sq[64];

    const int t = threadIdx.x;

    // ---- per-CTA setup: learned quant matrix into smem ----
    if (t < 64) {
        float nz = noise[0];
        float h1[16], h2[16];
#pragma unroll
        for (int k = 0; k < 16; k++) h1[k] = gelu_exact(nz * w1[k] + b1[k]);
#pragma unroll
        for (int k = 0; k < 16; k++) {
            float s = b2[k];
#pragma unroll
            for (int j = 0; j < 16; j++) s += h1[j] * w2[j * 16 + k];
            h2[k] = gelu_exact(s);
        }
        float nr[18];
#pragma unroll
        for (int k = 0; k < 18; k++) {
            float s = b3[k];
#pragma unroll
            for (int j = 0; j < 16; j++) s += h2[j] * w3[j * 18 + k];
            nr[k] = s;
        }
        float wmax = qmw[0];
#pragma unroll
        for (int i = 1; i < 16; i++) wmax = fmaxf(wmax, qmw[i]);
        float e[16], esum = 0.0f;
#pragma unroll
        for (int i = 0; i < 16; i++) { e[i] = expf(qmw[i] - wmax); esum += e[i]; }
        float inv = 1.0f / esum;

        float acc = 0.0f;
#pragma unroll
        for (int i = 0; i < 16; i++) {
            float coef = (e[i] * inv * nr[0] + nr[1]) * nr[2 + i];
            acc += coef * qmat[i * 64 + t];
        }
        sq[t] = acc;
    }
    __syncthreads();

    // ---- block geometry: one thread per 8x8 block ----
    const int b   = blockIdx.x * 128 + t;       // global block id
    const int img = b >> 6;
    const int by  = (b >> 3) & 7;
    const int bx  = b & 7;
    const long base = (long)img * 4096 + by * 512 + bx * 8;  // floats

    // ---- load + row DCT fused (xv lives 8 floats at a time) ----
    float w[64];
#pragma unroll
    for (int r = 0; r < 8; r++) {
        const float4* p = reinterpret_cast<const float4*>(x + base + r * 64);
        float4 a = __ldg(p), c = __ldg(p + 1);
        float xr[8] = {a.x, a.y, a.z, a.w, c.x, c.y, c.z, c.w};
#pragma unroll
        for (int m = 0; m < 8; m++) {
            float acc = 0.0f;
#pragma unroll
            for (int j = 0; j < 8; j++) acc = fmaf(xr[j], CD.v[m][j], acc);
            w[r * 8 + m] = acc;
        }
    }

    // ---- col DCT in place, mask by q, col IDCT in place ----
    const float4* sq4 = reinterpret_cast<const float4*>(sq);
#pragma unroll
    for (int c = 0; c < 8; c++) {
        float y[8];
#pragma unroll
        for (int r = 0; r < 8; r++) y[r] = w[r * 8 + c];
#pragma unroll
        for (int i = 0; i < 8; i++) {
            float acc = 0.0f;
#pragma unroll
            for (int r = 0; r < 8; r++) acc = fmaf(y[r], CD.v[i][r], acc);
            w[i * 8 + c] = acc;
        }
    }
#pragma unroll
    for (int k = 0; k < 16; k++) {
        float4 q = sq4[k];
        w[k * 4 + 0] *= q.x;
        w[k * 4 + 1] *= q.y;
        w[k * 4 + 2] *= q.z;
        w[k * 4 + 3] *= q.w;
    }
#pragma unroll
    for (int c = 0; c < 8; c++) {
        float z[8];
#pragma unroll
        for (int i = 0; i < 8; i++) z[i] = w[i * 8 + c];
#pragma unroll
        for (int a = 0; a < 8; a++) {
            float acc = 0.0f;
#pragma unroll
            for (int i = 0; i < 8; i++) acc = fmaf(z[i], CD.v[i][a], acc);
            w[a * 8 + c] = acc;
        }
    }

    // ---- row IDCT + re-read x (L2 hit) + high = x - low + stores ----
#pragma unroll
    for (int r = 0; r < 8; r++) {
        float tt[8];
#pragma unroll
        for (int m = 0; m < 8; m++) tt[m] = w[r * 8 + m];

        float lv[8];
#pragma unroll
        for (int bb = 0; bb < 8; bb++) {
            float acc = 0.0f;
#pragma unroll
            for (int m = 0; m < 8; m++) acc = fmaf(tt[m], CD.v[m][bb], acc);
            lv[bb] = acc;
        }

        const float4* p = reinterpret_cast<const float4*>(x + base + r * 64);
        float4 a = __ldg(p), c = __ldg(p + 1);

        float4* lp = reinterpret_cast<float4*>(lo + base + r * 64);
        lp[0] = make_float4(lv[0], lv[1], lv[2], lv[3]);
        lp[1] = make_float4(lv[4], lv[5], lv[6], lv[7]);
        float4* hp = reinterpret_cast<float4*>(hi + base + r * 64);
        hp[0] = make_float4(a.x - lv[0], a.y - lv[1], a.z - lv[2], a.w - lv[3]);
        hp[1] = make_float4(c.x - lv[4], c.y - lv[5], c.z - lv[6], c.w - lv[7]);
    }
}

// ---------------------------------------------------------------------------
// Launch: metadata order = x, noise_level, qmat, qmat_weights, w1,b1,w2,b2,w3,b3
// d_out = [low (N floats) | high (N floats)]
// ---------------------------------------------------------------------------
extern "C" void kernel_launch(void* const* d_in, const int* in_sizes, int n_in,
                              void* d_out, int out_size) {
    const float* x     = (const float*)d_in[0];
    const float* noise = (const float*)d_in[1];
    const float* qmat  = (const float*)d_in[2];
    const float* qmw   = (const float*)d_in[3];
    const float* w1    = (const float*)d_in[4];
    const float* b1    = (const float*)d_in[5];
    const float* w2    = (const float*)d_in[6];
    const float* b2    = (const float*)d_in[7];
    const float* w3    = (const float*)d_in[8];
    const float* b3    = (const float*)d_in[9];

    const int N       = in_sizes[0];   // 33554432
    const int nblocks = N / 64;        // 524288 8x8 blocks
    const int grid    = nblocks / 128;

    float* lo = (float*)d_out;
    float* hi = lo + N;

    fused_dct_kernel<<<grid, 128>>>(x, lo, hi, noise, qmat, qmw,
                                    w1, b1, w2, b2, w3, b3);
}

// round 9
// speedup vs baseline: 1.6223x; 1.6223x over previous
#include <cuda_runtime.h>
#include <math.h>

// ---------------------------------------------------------------------------
// Compile-time DCT-II matrix (matches reference: PI = 3.1415926 truncated).
// Entries are +/- 0.5*cos(k*pi/16) and sqrt(1/8); fold error vs reference
// < 4e-7. Function-local constexpr => every CD.v[const][const] becomes an
// FFMA immediate operand (imm-form FFMA, rt=1/SMSP; no LDS/LDC).
// ---------------------------------------------------------------------------
struct DCTTab { float v[8][8]; };

__host__ __device__ constexpr DCTTab make_dct() {
    const float ck[9] = {0.5f,        0.49039264f, 0.46193977f, 0.41573481f,
                         0.35355339f, 0.27778512f, 0.19134172f, 0.09754516f,
                         0.0f};
    DCTTab t{};
    for (int i = 0; i < 8; i++) {
        for (int j = 0; j < 8; j++) {
            if (i == 0) { t.v[i][j] = 0.35355339f; continue; }  // sqrt(1/8)
            int a = (i * (2 * j + 1)) % 32;
            float s = 1.0f;
            if (a > 16) a = 32 - a;                  // cos(2pi-x) =  cos(x)
            if (a > 8)  { a = 16 - a; s = -1.0f; }   // cos(pi-x)  = -cos(x)
            t.v[i][j] = s * ck[a];
        }
    }
    return t;
}

__device__ __forceinline__ float gelu_exact(float x) {
    return 0.5f * x * (1.0f + erff(x * 0.70710678f));
}

// ---------------------------------------------------------------------------
// Single fused kernel (one thread per 8x8 block, 128 threads/CTA).
//
// MLP setup is PHASED through shared memory so its register footprint is
// ~10 scalars (R7's inlined version cost +65 regs and tanked occupancy):
//   phase1: 16 thr -> h1[]   phase2: 16 thr -> h2[]   phase3: 18 thr -> nr[]
//   phase4: thread 0 serially does the 16-way softmax + coef[]  (~100 ops)
//   phase5: 64 thr reduce coef x qmat -> sq[64]
//
// x needed for "high = x - low" is stashed in PADDED smem (stride 17 float4:
// 8-thread LDS/STS phase hits banks 4t+4k, all distinct -> conflict-free),
// written and read only by the owning thread = private spill space. This
// frees the 64-register xv live range (R6) without re-reading gmem (R7).
// __launch_bounds__(128,4): regs <= 128 -> 4 CTAs/SM. smem 35.3KB x 4 fits.
// ---------------------------------------------------------------------------
#define XPITCH 17  // float4 units per thread slot (16 data + 1 pad)

__global__ void __launch_bounds__(128, 4)
fused_dct_kernel(const float* __restrict__ x,
                 float* __restrict__ lo,
                 float* __restrict__ hi,
                 const float* __restrict__ noise,
                 const float* __restrict__ qmat,
                 const float* __restrict__ qmw,
                 const float* __restrict__ w1, const float* __restrict__ b1,
                 const float* __restrict__ w2, const float* __restrict__ b2,
                 const float* __restrict__ w3, const float* __restrict__ b3) {
    constexpr DCTTab CD = make_dct();

    __shared__ __align__(16) float4 s_x[128 * XPITCH];   // 34816 B
    __shared__ __align__(16) float  sq[64];
    __shared__ float s_h1[16], s_h2[16], s_nr[18], s_coef[16];

    const int t = threadIdx.x;

    // ---- block geometry ----
    const int b   = blockIdx.x * 128 + t;       // global 8x8-block id
    const int img = b >> 6;
    const int by  = (b >> 3) & 7;
    const int bx  = b & 7;
    const long base  = (long)img * 4096 + by * 512 + bx * 8;  // floats
    const long base4 = base >> 2;                              // float4s

    // ---- issue all 16 x-loads up front (latency overlaps the MLP) ----
    const float4* xp = reinterpret_cast<const float4*>(x);
    float4 ld[16];
#pragma unroll
    for (int r = 0; r < 8; r++) {
        ld[2 * r]     = __ldg(xp + base4 + r * 16);
        ld[2 * r + 1] = __ldg(xp + base4 + r * 16 + 1);
    }

    // ---- phased MLP: tiny register footprint ----
    if (t < 16) s_h1[t] = gelu_exact(noise[0] * w1[t] + b1[t]);
    __syncthreads();
    if (t < 16) {
        float s = b2[t];
#pragma unroll
        for (int j = 0; j < 16; j++) s += s_h1[j] * w2[j * 16 + t];
        s_h2[t] = gelu_exact(s);
    }
    __syncthreads();
    if (t < 18) {
        float s = b3[t];
#pragma unroll
        for (int j = 0; j < 16; j++) s += s_h2[j] * w3[j * 18 + t];
        s_nr[t] = s;
    }
    __syncthreads();
    if (t == 0) {
        float wmax = qmw[0];
#pragma unroll
        for (int i = 1; i < 16; i++) wmax = fmaxf(wmax, qmw[i]);
        float esum = 0.0f;
#pragma unroll
        for (int i = 0; i < 16; i++) esum += expf(qmw[i] - wmax);
        float inv = 1.0f / esum;
        float nr0 = s_nr[0], nr1 = s_nr[1];
#pragma unroll
        for (int i = 0; i < 16; i++)
            s_coef[i] = (expf(qmw[i] - wmax) * inv * nr0 + nr1) * s_nr[2 + i];
    }
    __syncthreads();
    if (t < 64) {
        float acc = 0.0f;
#pragma unroll
        for (int i = 0; i < 16; i++) acc += s_coef[i] * qmat[i * 64 + t];
        sq[t] = acc;
    }
    __syncthreads();

    // ---- stash x in private smem + row DCT (consumes ld regs) ----
    float4* xs = &s_x[t * XPITCH];
    float w[64];
#pragma unroll
    for (int r = 0; r < 8; r++) {
        float4 a = ld[2 * r], c = ld[2 * r + 1];
        xs[2 * r]     = a;
        xs[2 * r + 1] = c;
        float xr[8] = {a.x, a.y, a.z, a.w, c.x, c.y, c.z, c.w};
#pragma unroll
        for (int m = 0; m < 8; m++) {
            float acc = 0.0f;
#pragma unroll
            for (int j = 0; j < 8; j++) acc = fmaf(xr[j], CD.v[m][j], acc);
            w[r * 8 + m] = acc;
        }
    }

    // ---- col DCT in place ----
#pragma unroll
    for (int c = 0; c < 8; c++) {
        float y[8];
#pragma unroll
        for (int r = 0; r < 8; r++) y[r] = w[r * 8 + c];
#pragma unroll
        for (int i = 0; i < 8; i++) {
            float acc = 0.0f;
#pragma unroll
            for (int r = 0; r < 8; r++) acc = fmaf(y[r], CD.v[i][r], acc);
            w[i * 8 + c] = acc;
        }
    }

    // ---- spectral mask (warp-uniform float4 broadcasts) ----
    const float4* sq4 = reinterpret_cast<const float4*>(sq);
#pragma unroll
    for (int k = 0; k < 16; k++) {
        float4 q = sq4[k];
        w[k * 4 + 0] *= q.x;
        w[k * 4 + 1] *= q.y;
        w[k * 4 + 2] *= q.z;
        w[k * 4 + 3] *= q.w;
    }

    // ---- col IDCT in place ----
#pragma unroll
    for (int c = 0; c < 8; c++) {
        float z[8];
#pragma unroll
        for (int i = 0; i < 8; i++) z[i] = w[i * 8 + c];
#pragma unroll
        for (int a = 0; a < 8; a++) {
            float acc = 0.0f;
#pragma unroll
            for (int i = 0; i < 8; i++) acc = fmaf(z[i], CD.v[i][a], acc);
            w[a * 8 + c] = acc;
        }
    }

    // ---- row IDCT + read x back from smem + high = x - low + stores ----
#pragma unroll
    for (int r = 0; r < 8; r++) {
        float tt[8];
#pragma unroll
        for (int m = 0; m < 8; m++) tt[m] = w[r * 8 + m];

        float lv[8];
#pragma unroll
        for (int bb = 0; bb < 8; bb++) {
            float acc = 0.0f;
#pragma unroll
            for (int m = 0; m < 8; m++) acc = fmaf(tt[m], CD.v[m][bb], acc);
            lv[bb] = acc;
        }

        float4 a = xs[2 * r], c = xs[2 * r + 1];

        float4* lp = reinterpret_cast<float4*>(lo + base + r * 64);
        lp[0] = make_float4(lv[0], lv[1], lv[2], lv[3]);
        lp[1] = make_float4(lv[4], lv[5], lv[6], lv[7]);
        float4* hp = reinterpret_cast<float4*>(hi + base + r * 64);
        hp[0] = make_float4(a.x - lv[0], a.y - lv[1], a.z - lv[2], a.w - lv[3]);
        hp[1] = make_float4(c.x - lv[4], c.y - lv[5], c.z - lv[6], c.w - lv[7]);
    }
}

// ---------------------------------------------------------------------------
// Launch: metadata order = x, noise_level, qmat, qmat_weights, w1,b1,w2,b2,w3,b3
// d_out = [low (N floats) | high (N floats)]
// ---------------------------------------------------------------------------
extern "C" void kernel_launch(void* const* d_in, const int* in_sizes, int n_in,
                              void* d_out, int out_size) {
    const float* x     = (const float*)d_in[0];
    const float* noise = (const float*)d_in[1];
    const float* qmat  = (const float*)d_in[2];
    const float* qmw   = (const float*)d_in[3];
    const float* w1    = (const float*)d_in[4];
    const float* b1    = (const float*)d_in[5];
    const float* w2    = (const float*)d_in[6];
    const float* b2    = (const float*)d_in[7];
    const float* w3    = (const float*)d_in[8];
    const float* b3    = (const float*)d_in[9];

    const int N       = in_sizes[0];   // 33554432
    const int nblocks = N / 64;        // 524288 8x8 blocks
    const int grid    = nblocks / 128;

    float* lo = (float*)d_out;
    float* hi = lo + N;

    fused_dct_kernel<<<grid, 128>>>(x, lo, hi, noise, qmat, qmw,
                                    w1, b1, w2, b2, w3, b3);
}